// round 3
// baseline (speedup 1.0000x reference)
#include <cuda_runtime.h>

#define BATCH 16
#define NT 3
#define NSEQ 1024
#define IND 512
#define FD 256
#define NLAY 3
#define NWRD 32
#define ALPHAV 0.2f
#define NEGV -9e15f

// ---------------- scratch (device globals; no allocations allowed) ----------
__device__ unsigned g_mask[NLAY][BATCH * NT * NSEQ * NWRD];
__device__ float g_h[(size_t)9 * BATCH * NSEQ * FD];
__device__ float g_f1[9 * BATCH * NSEQ];
__device__ float g_f2[9 * BATCH * NSEQ];
__device__ float g_att[(size_t)BATCH * NSEQ * NSEQ];
__device__ float g_H[(size_t)BATCH * NSEQ * NLAY * FD];

// ---------------- adj -> bitset --------------------------------------------
__global__ void bits_kernel(const float* __restrict__ adj) {
    int r = blockIdx.x;
    int tid = threadIdx.x;
    float v = adj[(size_t)r * NSEQ + tid];
    unsigned bal = __ballot_sync(0xffffffffu, v > 0.0f);
    if ((tid & 31) == 0) g_mask[0][(size_t)r * NWRD + (tid >> 5)] = bal;
}

__global__ void bmm_kernel(int src, int dst) {
    int r = blockIdx.x;
    int bt = r / NSEQ;
    int lane = threadIdx.x;
    const unsigned* lrow = &g_mask[src][(size_t)r * NWRD];
    const unsigned* rbase = &g_mask[0][(size_t)bt * NSEQ * NWRD];
    unsigned myw = lrow[lane];
    unsigned acc = 0;
    #pragma unroll 1
    for (int w = 0; w < NWRD; ++w) {
        unsigned bitsw = __shfl_sync(0xffffffffu, myw, w);
        while (bitsw) {
            int j = (w << 5) + (__ffs(bitsw) - 1);
            bitsw &= bitsw - 1;
            acc |= rbase[(size_t)j * NWRD + lane];
        }
    }
    g_mask[dst][(size_t)r * NWRD + lane] = acc;
}

// ---------------- tf32 tensor-core GEMM (128x128 tile, BK=16) ---------------
// A [M,K] row-major, B [K,N] row-major, C [M,N]. M%128==0, N%128==0, K%16==0.
__device__ __forceinline__ unsigned cvt_tf32(float x) {
    unsigned r;
    asm("cvt.rna.tf32.f32 %0, %1;" : "=r"(r) : "f"(x));
    return r;
}

#define BM 128
#define BN 128
#define BK 16

__global__ __launch_bounds__(256) void tgemm(
    const float* __restrict__ A, const float* __restrict__ Bm, float* __restrict__ C,
    int Kk, int lda, int ldb, int ldc,
    long long sA, long long sB, long long sC, int accum)
{
    int z = blockIdx.z;
    A  += (size_t)z * sA;
    Bm += (size_t)z * sB;
    C  += (size_t)z * sC;

    // fragment-major smem:
    // Asm[stage][ktile(2)][mtile(8)][lane(32)][reg(4)]
    // Bsm[stage][ktile(2)][ntile(16)][lane(32)][reg(2)]
    __shared__ unsigned Asm[2][2][8][32][4];
    __shared__ unsigned Bsm[2][2][16][32][2];

    int tid = threadIdx.x;
    int lane = tid & 31;
    int wid = tid >> 5;
    int wm = wid >> 2;          // 0..1  (warp m index, 64 rows each)
    int wn = wid & 3;           // 0..3  (warp n index, 32 cols each)

    int bm = blockIdx.y * BM, bn = blockIdx.x * BN;

    // global A load: thread -> rows tid/4 and tid/4+64, cols (tid%4)*4 .. +3
    int aRow0 = tid >> 2;
    int aK0 = (tid & 3) * 4;
    const float* Ap0 = A + (size_t)(bm + aRow0) * lda + aK0;
    const float* Ap1 = A + (size_t)(bm + aRow0 + 64) * lda + aK0;
    // global B load: thread -> rows tid/32 and tid/32+8, cols (tid%32)*4
    int bRow0 = tid >> 5;
    int bN0 = (tid & 31) * 4;
    const float* Bp0 = Bm + (size_t)bRow0 * ldb + bn + bN0;
    const float* Bp1 = Bm + (size_t)(bRow0 + 8) * ldb + bn + bN0;

    float d[4][4][4];
    #pragma unroll
    for (int i = 0; i < 4; i++)
        #pragma unroll
        for (int j = 0; j < 4; j++)
            #pragma unroll
            for (int r = 0; r < 4; r++) d[i][j][r] = 0.0f;

    float4 a0 = *(const float4*)Ap0;
    float4 a1v = *(const float4*)Ap1;
    float4 b0 = *(const float4*)Bp0;
    float4 b1 = *(const float4*)Bp1;

    // staging helpers ---------------------------------------------------
    // A value at (m in 0..127, k in 0..15):
    //   mtile=m/16, mr=m%16, ktile=k/8, kin=k%8
    //   lane=(mr%8)*4 + (kin%4), reg=(mr/8) + 2*(kin/4)
    int amt0 = aRow0 >> 4, amr0 = aRow0 & 15;
    int amt1 = (aRow0 + 64) >> 4, amr1 = (aRow0 + 64) & 15;
    int aktile = aK0 >> 3;            // aK0 in {0,4,8,12} -> ktile = 0,0,1,1
    int akhi = (aK0 & 7) >> 2;        // kin/4 component (0 or 1)
    // B value at (k in 0..15, n in 0..127):
    //   ntile=n/8, nin=n%8, ktile=k/8, kin=k%8
    //   lane=nin*4 + (kin%4), reg=kin/4
    int bkt0 = bRow0 >> 3, bkin0 = bRow0 & 7;
    int bkt1 = (bRow0 + 8) >> 3, bkin1 = (bRow0 + 8) & 7;

    #define STAGE_A(st, v4, mt, mr)                                          \
        {                                                                    \
            float vv[4] = {(v4).x, (v4).y, (v4).z, (v4).w};                  \
            _Pragma("unroll")                                                \
            for (int i = 0; i < 4; i++)                                      \
                Asm[st][aktile][mt][((mr) & 7) * 4 + i][((mr) >> 3) + 2 * akhi] \
                    = cvt_tf32(vv[i]);                                       \
        }
    #define STAGE_B(st, v4, kt, kin)                                         \
        {                                                                    \
            float vv[4] = {(v4).x, (v4).y, (v4).z, (v4).w};                  \
            _Pragma("unroll")                                                \
            for (int i = 0; i < 4; i++) {                                    \
                int n = bN0 + i;                                             \
                Bsm[st][kt][n >> 3][(n & 7) * 4 + ((kin) & 3)][(kin) >> 2]    \
                    = cvt_tf32(vv[i]);                                       \
            }                                                                \
        }

    STAGE_A(0, a0, amt0, amr0);
    STAGE_A(0, a1v, amt1, amr1);
    STAGE_B(0, b0, bkt0, bkin0);
    STAGE_B(0, b1, bkt1, bkin1);
    __syncthreads();

    int nIter = Kk >> 4;
    for (int it = 0; it < nIter; it++) {
        int cur = it & 1;
        if (it + 1 < nIter) {
            int off = (it + 1) * BK;
            a0  = *(const float4*)(Ap0 + off);
            a1v = *(const float4*)(Ap1 + off);
            b0  = *(const float4*)(Bp0 + (size_t)off * ldb);
            b1  = *(const float4*)(Bp1 + (size_t)off * ldb);
        }
        #pragma unroll
        for (int kt = 0; kt < 2; kt++) {
            unsigned af[4][4];
            unsigned bf[4][2];
            #pragma unroll
            for (int mt = 0; mt < 4; mt++) {
                uint4 t = *(const uint4*)(&Asm[cur][kt][wm * 4 + mt][lane][0]);
                af[mt][0] = t.x; af[mt][1] = t.y; af[mt][2] = t.z; af[mt][3] = t.w;
            }
            #pragma unroll
            for (int nt = 0; nt < 4; nt++) {
                uint2 t = *(const uint2*)(&Bsm[cur][kt][wn * 4 + nt][lane][0]);
                bf[nt][0] = t.x; bf[nt][1] = t.y;
            }
            #pragma unroll
            for (int mt = 0; mt < 4; mt++)
                #pragma unroll
                for (int nt = 0; nt < 4; nt++) {
                    asm volatile(
                        "mma.sync.aligned.m16n8k8.row.col.f32.tf32.tf32.f32 "
                        "{%0,%1,%2,%3}, {%4,%5,%6,%7}, {%8,%9}, {%0,%1,%2,%3};"
                        : "+f"(d[mt][nt][0]), "+f"(d[mt][nt][1]),
                          "+f"(d[mt][nt][2]), "+f"(d[mt][nt][3])
                        : "r"(af[mt][0]), "r"(af[mt][1]),
                          "r"(af[mt][2]), "r"(af[mt][3]),
                          "r"(bf[nt][0]), "r"(bf[nt][1]));
                }
        }
        if (it + 1 < nIter) {
            int nxt = cur ^ 1;
            STAGE_A(nxt, a0, amt0, amr0);
            STAGE_A(nxt, a1v, amt1, amr1);
            STAGE_B(nxt, b0, bkt0, bkin0);
            STAGE_B(nxt, b1, bkt1, bkin1);
            __syncthreads();
        }
    }

    // epilogue: thread holds C rows (lane>>2, lane>>2+8) cols 2*(lane&3)+{0,1}
    int cr = lane >> 2;
    int cc = (lane & 3) * 2;
    #pragma unroll
    for (int mt = 0; mt < 4; mt++) {
        #pragma unroll
        for (int half = 0; half < 2; half++) {
            int row = bm + wm * 64 + mt * 16 + cr + half * 8;
            float* cp = C + (size_t)row * ldc + bn + wn * 32 + cc;
            #pragma unroll
            for (int nt = 0; nt < 4; nt++) {
                float2 v = make_float2(d[mt][nt][half * 2], d[mt][nt][half * 2 + 1]);
                float* p = cp + nt * 8;
                if (accum) {
                    float2 o = *(const float2*)p;
                    v.x += o.x; v.y += o.y;
                }
                *(float2*)p = v;
            }
        }
    }
}

// ---------------- f1/f2 -----------------------------------------------------
__global__ void f_kernel(const float* __restrict__ a1, const float* __restrict__ a2) {
    int gw = (blockIdx.x * blockDim.x + threadIdx.x) >> 5;
    int lane = threadIdx.x & 31;
    if (gw >= 9 * BATCH * NSEQ) return;
    int z = gw / (BATCH * NSEQ);
    const float* hp = &g_h[(size_t)gw * FD];
    const float* a1p = a1 + (size_t)z * FD;
    const float* a2p = a2 + (size_t)z * FD;
    float s1 = 0.0f, s2 = 0.0f;
    #pragma unroll
    for (int i = lane; i < FD; i += 32) {
        float hv = hp[i];
        s1 = fmaf(hv, a1p[i], s1);
        s2 = fmaf(hv, a2p[i], s2);
    }
    #pragma unroll
    for (int off = 16; off > 0; off >>= 1) {
        s1 += __shfl_down_sync(0xffffffffu, s1, off);
        s2 += __shfl_down_sync(0xffffffffu, s2, off);
    }
    if (lane == 0) { g_f1[gw] = s1; g_f2[gw] = s2; }
}

// ---------------- fused sparse softmax + SpMM (layers k=0,1) ----------------
__global__ __launch_bounds__(256) void spmm_kernel(int k, float* __restrict__ Hout) {
    int n = blockIdx.x, b = blockIdx.y;
    int tid = threadIdx.x;

    __shared__ int   list[NSEQ];
    __shared__ float pn[NSEQ];
    __shared__ int   s_cnt;
    __shared__ float red[256];

    float acc = 0.0f;

    for (int t = 0; t < NT; t++) {
        int z = t * 3 + k;
        if (tid == 0) s_cnt = 0;
        __syncthreads();
        if (tid < NWRD) {
            unsigned w = g_mask[k][(((size_t)b * NT + t) * NSEQ + n) * NWRD + tid];
            while (w) {
                int j = (tid << 5) + (__ffs(w) - 1);
                w &= w - 1;
                int p = atomicAdd(&s_cnt, 1);
                list[p] = j;
            }
        }
        __syncthreads();
        int cnt = s_cnt;

        const float* f2p = &g_f2[(size_t)z * BATCH * NSEQ + (size_t)b * NSEQ];
        float f1v = g_f1[(size_t)z * BATCH * NSEQ + (size_t)b * NSEQ + n];
        const float* hp = &g_h[((size_t)z * BATCH + b) * NSEQ * FD];

        if (cnt == 0) {
            float a = 0.0f;
            for (int j = 0; j < NSEQ; j++) a += hp[(size_t)j * FD + tid];
            acc += a * (1.0f / NSEQ);
            __syncthreads();
            continue;
        }

        float lmax = -1e30f;
        for (int i = tid; i < cnt; i += 256) {
            float x = f1v + f2p[list[i]];
            x = (x > 0.0f) ? x : ALPHAV * x;
            pn[i] = x;
            lmax = fmaxf(lmax, x);
        }
        red[tid] = lmax;
        __syncthreads();
        for (int s = 128; s > 0; s >>= 1) {
            if (tid < s) red[tid] = fmaxf(red[tid], red[tid + s]);
            __syncthreads();
        }
        float m = red[0];
        __syncthreads();

        float lsum = 0.0f;
        for (int i = tid; i < cnt; i += 256) {
            float p = __expf(pn[i] - m);
            pn[i] = p;
            lsum += p;
        }
        red[tid] = lsum;
        __syncthreads();
        for (int s = 128; s > 0; s >>= 1) {
            if (tid < s) red[tid] += red[tid + s];
            __syncthreads();
        }
        float inv = 1.0f / red[0];
        __syncthreads();

        int i = 0;
        for (; i + 4 <= cnt; i += 4) {
            int j0 = list[i], j1 = list[i + 1], j2 = list[i + 2], j3 = list[i + 3];
            float p0 = pn[i] * inv, p1 = pn[i + 1] * inv;
            float p2 = pn[i + 2] * inv, p3 = pn[i + 3] * inv;
            float h0 = hp[(size_t)j0 * FD + tid];
            float h1 = hp[(size_t)j1 * FD + tid];
            float h2 = hp[(size_t)j2 * FD + tid];
            float h3 = hp[(size_t)j3 * FD + tid];
            acc = fmaf(p0, h0, acc);
            acc = fmaf(p1, h1, acc);
            acc = fmaf(p2, h2, acc);
            acc = fmaf(p3, h3, acc);
        }
        for (; i < cnt; i++)
            acc = fmaf(pn[i] * inv, hp[(size_t)list[i] * FD + tid], acc);
        __syncthreads();
    }

    Hout[(((size_t)b * NSEQ + n) * NLAY + k) * FD + tid] = acc;
}

// ---------------- dense masked-softmax attention row (k=2) ------------------
__global__ void att_kernel(int t, int k) {
    int i = blockIdx.x, b = blockIdx.y;
    int tid = threadIdx.x;
    int z = t * 3 + k;

    __shared__ float sf2[NSEQ];
    __shared__ unsigned smask[NWRD];
    __shared__ float red[256];

    const float* f2p = &g_f2[(size_t)z * BATCH * NSEQ + (size_t)b * NSEQ];
    for (int j = tid; j < NSEQ; j += 256) sf2[j] = f2p[j];
    if (tid < NWRD)
        smask[tid] = g_mask[k][(((size_t)b * NT + t) * NSEQ + i) * NWRD + tid];
    __syncthreads();

    float f1v = g_f1[(size_t)z * BATCH * NSEQ + (size_t)b * NSEQ + i];

    float e[4];
    bool msk[4];
    float lmax = NEGV;
    #pragma unroll
    for (int q = 0; q < 4; q++) {
        int j = tid + q * 256;
        bool m = (smask[j >> 5] >> (j & 31)) & 1u;
        float x = f1v + sf2[j];
        x = (x > 0.0f) ? x : ALPHAV * x;
        e[q] = m ? x : NEGV;
        msk[q] = m;
        lmax = fmaxf(lmax, e[q]);
    }
    red[tid] = lmax;
    __syncthreads();
    for (int s = 128; s > 0; s >>= 1) {
        if (tid < s) red[tid] = fmaxf(red[tid], red[tid + s]);
        __syncthreads();
    }
    float m = red[0];
    __syncthreads();

    bool empty = (m < -8.9e15f);
    float p[4];
    float lsum = 0.0f;
    #pragma unroll
    for (int q = 0; q < 4; q++) {
        p[q] = empty ? 1.0f : (msk[q] ? __expf(e[q] - m) : 0.0f);
        lsum += p[q];
    }
    red[tid] = lsum;
    __syncthreads();
    for (int s = 128; s > 0; s >>= 1) {
        if (tid < s) red[tid] += red[tid + s];
        __syncthreads();
    }
    float inv = 1.0f / red[0];

    float* arow = &g_att[((size_t)b * NSEQ + i) * NSEQ];
    #pragma unroll
    for (int q = 0; q < 4; q++) arow[tid + q * 256] = p[q] * inv;
}

// ---------------- final combine ---------------------------------------------
__global__ void combine_kernel(const float* __restrict__ Ww, const float* __restrict__ bw,
                               const float* __restrict__ Wc, float* __restrict__ out) {
    int bn = blockIdx.x;
    int tid = threadIdx.x;
    __shared__ float sh[NLAY * FD];
    __shared__ float part[NLAY][128];
    __shared__ float sy[NLAY];

    const float* Hp = &g_H[(size_t)bn * NLAY * FD];
    for (int i = tid; i < NLAY * FD; i += 128) sh[i] = Hp[i];
    __syncthreads();

    float loc[NLAY] = {0.0f, 0.0f, 0.0f};
    if (tid < 100) {
        float wc = Wc[tid];
        float bwv = bw[tid];
        #pragma unroll
        for (int k = 0; k < NLAY; k++) {
            float y = bwv;
            #pragma unroll 8
            for (int i = 0; i < FD; i++)
                y = fmaf(sh[k * FD + i], Ww[i * 100 + tid], y);
            loc[k] = tanhf(y) * wc;
        }
    }
    #pragma unroll
    for (int k = 0; k < NLAY; k++) part[k][tid] = loc[k];
    __syncthreads();
    for (int s = 64; s > 0; s >>= 1) {
        if (tid < s) {
            part[0][tid] += part[0][tid + s];
            part[1][tid] += part[1][tid + s];
            part[2][tid] += part[2][tid + s];
        }
        __syncthreads();
    }
    if (tid == 0) {
        float s0 = part[0][0], s1 = part[1][0], s2 = part[2][0];
        float mx = fmaxf(s0, fmaxf(s1, s2));
        float e0 = __expf(s0 - mx), e1 = __expf(s1 - mx), e2 = __expf(s2 - mx);
        float invs = 1.0f / (e0 + e1 + e2);
        sy[0] = e0 * invs; sy[1] = e1 * invs; sy[2] = e2 * invs;
    }
    __syncthreads();

    float w0 = sy[0], w1 = sy[1], w2 = sy[2];
    for (int f = tid; f < FD; f += 128)
        out[(size_t)bn * FD + f] =
            w0 * sh[f] + w1 * sh[FD + f] + w2 * sh[2 * FD + f];
}

// ---------------- launch ----------------------------------------------------
extern "C" void kernel_launch(void* const* d_in, const int* in_sizes, int n_in,
                              void* d_out, int out_size) {
    const float* adj = (const float*)d_in[0];
    const float* X   = (const float*)d_in[1];
    const float* W   = (const float*)d_in[2];
    const float* a1  = (const float*)d_in[3];
    const float* a2  = (const float*)d_in[4];
    const float* Ww  = (const float*)d_in[5];
    const float* bw  = (const float*)d_in[6];
    const float* Wc  = (const float*)d_in[7];
    float* out = (float*)d_out;

    void *ph, *patt, *pH;
    cudaGetSymbolAddress(&ph, g_h);
    cudaGetSymbolAddress(&patt, g_att);
    cudaGetSymbolAddress(&pH, g_H);
    float* hbuf = (float*)ph;
    float* attbuf = (float*)patt;
    float* Hbuf = (float*)pH;

    // 1. adjacency bitsets + boolean powers
    bits_kernel<<<BATCH * NT * NSEQ, 1024>>>(adj);
    bmm_kernel<<<BATCH * NT * NSEQ, 32>>>(0, 1);
    bmm_kernel<<<BATCH * NT * NSEQ, 32>>>(1, 2);

    // 2. h[t,k] = X @ W[t,k]  (tf32 tensor cores)
    {
        dim3 grid(FD / BN, (BATCH * NSEQ) / BM, 9);
        tgemm<<<grid, 256>>>(X, W, hbuf,
                             IND, IND, FD, FD,
                             0LL, (long long)IND * FD,
                             (long long)BATCH * NSEQ * FD, 0);
    }

    // 3. f1/f2 projections
    f_kernel<<<(9 * BATCH * NSEQ) / 8, 256>>>(a1, a2);

    // 4a. sparse layers k=0,1
    spmm_kernel<<<dim3(NSEQ, BATCH), 256>>>(0, Hbuf);
    spmm_kernel<<<dim3(NSEQ, BATCH), 256>>>(1, Hbuf);

    // 4b. dense layer k=2: masked softmax + tf32 GEMM accumulated over t
    for (int t = 0; t < NT; t++) {
        att_kernel<<<dim3(NSEQ, BATCH), 256>>>(t, 2);
        int z = t * 3 + 2;
        dim3 grid(FD / BN, NSEQ / BM, BATCH);
        tgemm<<<grid, 256>>>(attbuf,
                             hbuf + (size_t)z * BATCH * NSEQ * FD,
                             Hbuf + 2 * FD,
                             NSEQ, NSEQ, FD, NLAY * FD,
                             (long long)NSEQ * NSEQ,
                             (long long)NSEQ * FD,
                             (long long)NSEQ * NLAY * FD,
                             t > 0 ? 1 : 0);
    }

    // 5. combine
    combine_kernel<<<BATCH * NSEQ, 128>>>(Ww, bw, Wc, out);
}

// round 4
// speedup vs baseline: 1.3920x; 1.3920x over previous
#include <cuda_runtime.h>

#define BATCH 16
#define NT 3
#define NSEQ 1024
#define IND 512
#define FD 256
#define NLAY 3
#define NWRD 32
#define ALPHAV 0.2f
#define NEGV -9e15f

// ---------------- scratch (device globals; no allocations allowed) ----------
__device__ unsigned g_mask[NLAY][BATCH * NT * NSEQ * NWRD];
__device__ float g_h[(size_t)9 * BATCH * NSEQ * FD];
__device__ float g_f1[9 * BATCH * NSEQ];
__device__ float g_f2[9 * BATCH * NSEQ];
__device__ float g_att[(size_t)BATCH * NSEQ * NSEQ];
__device__ float g_H[(size_t)BATCH * NSEQ * NLAY * FD];

// ---------------- adj -> bitset --------------------------------------------
__global__ void bits_kernel(const float* __restrict__ adj) {
    int r = blockIdx.x;
    int tid = threadIdx.x;
    float v = adj[(size_t)r * NSEQ + tid];
    unsigned bal = __ballot_sync(0xffffffffu, v > 0.0f);
    if ((tid & 31) == 0) g_mask[0][(size_t)r * NWRD + (tid >> 5)] = bal;
}

__global__ void bmm_kernel(int src, int dst) {
    int r = blockIdx.x;
    int bt = r / NSEQ;
    int lane = threadIdx.x;
    const unsigned* lrow = &g_mask[src][(size_t)r * NWRD];
    const unsigned* rbase = &g_mask[0][(size_t)bt * NSEQ * NWRD];
    unsigned myw = lrow[lane];
    unsigned acc = 0;
    #pragma unroll 1
    for (int w = 0; w < NWRD; ++w) {
        unsigned bitsw = __shfl_sync(0xffffffffu, myw, w);
        while (bitsw) {
            int j = (w << 5) + (__ffs(bitsw) - 1);
            bitsw &= bitsw - 1;
            acc |= rbase[(size_t)j * NWRD + lane];
        }
    }
    g_mask[dst][(size_t)r * NWRD + lane] = acc;
}

// ---------------- tf32 tensor-core GEMM (128x128 tile, BK=16) ---------------
__device__ __forceinline__ unsigned cvt_tf32(float x) {
    unsigned r;
    asm("cvt.rna.tf32.f32 %0, %1;" : "=r"(r) : "f"(x));
    return r;
}

#define BM 128
#define BN 128
#define BK 16

__global__ __launch_bounds__(256) void tgemm(
    const float* __restrict__ A, const float* __restrict__ Bm, float* __restrict__ C,
    int Kk, int lda, int ldb, int ldc,
    long long sA, long long sB, long long sC, int accum)
{
    int z = blockIdx.z;
    A  += (size_t)z * sA;
    Bm += (size_t)z * sB;
    C  += (size_t)z * sC;

    // fragment-major smem:
    // Asm[stage][ktile(2)][mtile(8)][lane(32)][reg(4)]
    // Bsm[stage][ktile(2)][ntile(16)][lane(32)][reg(2)]
    __shared__ unsigned Asm[2][2][8][32][4];
    __shared__ unsigned Bsm[2][2][16][32][2];

    int tid = threadIdx.x;
    int lane = tid & 31;
    int wid = tid >> 5;
    int wm = wid >> 2;          // compute-warp m index (64 rows)
    int wn = wid & 3;           // compute-warp n index (32 cols)

    int bm = blockIdx.y * BM, bn = blockIdx.x * BN;

    int lane4 = lane >> 2;      // fragment row group / n group
    int lanek = lane & 3;       // fragment k in group

    // --- staging assignment (per warp) ---
    // A: warp wid stages mtile = wid (rows bm+16*wid .. +15), ktiles 0,1
    //    thread loads A(r,k),(r+8,k),(r,k+4),(r+8,k+4), r=lane4, k=8q+lanek
    const float* Arow0 = A + (size_t)(bm + wid * 16 + lane4) * lda + lanek;
    const float* Arow8 = Arow0 + (size_t)8 * lda;
    // B: warp wid stages kt = wid>>2, ntiles 4*(wid&3) .. +3
    //    thread loads B(k,n),(k+4,n), k=8*kt+lanek, n=bn+8*nt+lane4
    int bkt = wid >> 2;
    int bnt0 = (wid & 3) * 4;
    const float* Bbase = Bm + (size_t)(bkt * 8 + lanek) * ldb + bn + lane4;

    float d[4][4][4];
    #pragma unroll
    for (int i = 0; i < 4; i++)
        #pragma unroll
        for (int j = 0; j < 4; j++)
            #pragma unroll
            for (int r = 0; r < 4; r++) d[i][j][r] = 0.0f;

    float av[2][4];   // [q][reg]
    float bv[4][2];   // [frag][reg]

    #define LOAD_GLOBAL(koff)                                               \
        {                                                                   \
            _Pragma("unroll")                                               \
            for (int q = 0; q < 2; q++) {                                   \
                int kk = (koff) + q * 8;                                    \
                av[q][0] = Arow0[kk];                                       \
                av[q][1] = Arow8[kk];                                       \
                av[q][2] = Arow0[kk + 4];                                   \
                av[q][3] = Arow8[kk + 4];                                   \
            }                                                               \
            _Pragma("unroll")                                               \
            for (int f = 0; f < 4; f++) {                                   \
                const float* bp = Bbase + (size_t)(koff) * ldb + (bnt0 + f) * 8; \
                bv[f][0] = bp[0];                                           \
                bv[f][1] = bp[(size_t)4 * ldb];                             \
            }                                                               \
        }

    #define STORE_STAGE(st)                                                 \
        {                                                                   \
            _Pragma("unroll")                                               \
            for (int q = 0; q < 2; q++) {                                   \
                uint4 t;                                                    \
                t.x = cvt_tf32(av[q][0]); t.y = cvt_tf32(av[q][1]);         \
                t.z = cvt_tf32(av[q][2]); t.w = cvt_tf32(av[q][3]);         \
                *(uint4*)(&Asm[st][q][wid][lane][0]) = t;                   \
            }                                                               \
            _Pragma("unroll")                                               \
            for (int f = 0; f < 4; f++) {                                   \
                uint2 t;                                                    \
                t.x = cvt_tf32(bv[f][0]); t.y = cvt_tf32(bv[f][1]);         \
                *(uint2*)(&Bsm[st][bkt][bnt0 + f][lane][0]) = t;            \
            }                                                               \
        }

    LOAD_GLOBAL(0);
    STORE_STAGE(0);
    __syncthreads();

    int nIter = Kk >> 4;
    for (int it = 0; it < nIter; it++) {
        int cur = it & 1;
        if (it + 1 < nIter) LOAD_GLOBAL((it + 1) * BK);
        #pragma unroll
        for (int kt = 0; kt < 2; kt++) {
            unsigned af[4][4];
            unsigned bf[4][2];
            #pragma unroll
            for (int mt = 0; mt < 4; mt++) {
                uint4 t = *(const uint4*)(&Asm[cur][kt][wm * 4 + mt][lane][0]);
                af[mt][0] = t.x; af[mt][1] = t.y; af[mt][2] = t.z; af[mt][3] = t.w;
            }
            #pragma unroll
            for (int nt = 0; nt < 4; nt++) {
                uint2 t = *(const uint2*)(&Bsm[cur][kt][wn * 4 + nt][lane][0]);
                bf[nt][0] = t.x; bf[nt][1] = t.y;
            }
            #pragma unroll
            for (int mt = 0; mt < 4; mt++)
                #pragma unroll
                for (int nt = 0; nt < 4; nt++) {
                    asm volatile(
                        "mma.sync.aligned.m16n8k8.row.col.f32.tf32.tf32.f32 "
                        "{%0,%1,%2,%3}, {%4,%5,%6,%7}, {%8,%9}, {%0,%1,%2,%3};"
                        : "+f"(d[mt][nt][0]), "+f"(d[mt][nt][1]),
                          "+f"(d[mt][nt][2]), "+f"(d[mt][nt][3])
                        : "r"(af[mt][0]), "r"(af[mt][1]),
                          "r"(af[mt][2]), "r"(af[mt][3]),
                          "r"(bf[nt][0]), "r"(bf[nt][1]));
                }
        }
        if (it + 1 < nIter) {
            __syncthreads();
            STORE_STAGE(cur ^ 1);
            __syncthreads();
        }
    }

    int cr = lane >> 2;
    int cc = (lane & 3) * 2;
    #pragma unroll
    for (int mt = 0; mt < 4; mt++) {
        #pragma unroll
        for (int half = 0; half < 2; half++) {
            int row = bm + wm * 64 + mt * 16 + cr + half * 8;
            float* cp = C + (size_t)row * ldc + bn + wn * 32 + cc;
            #pragma unroll
            for (int nt = 0; nt < 4; nt++) {
                float2 v = make_float2(d[mt][nt][half * 2], d[mt][nt][half * 2 + 1]);
                float* p = cp + nt * 8;
                if (accum) {
                    float2 o = *(const float2*)p;
                    v.x += o.x; v.y += o.y;
                }
                *(float2*)p = v;
            }
        }
    }
}

// ---------------- f1/f2 -----------------------------------------------------
__global__ void f_kernel(const float* __restrict__ a1, const float* __restrict__ a2) {
    int gw = (blockIdx.x * blockDim.x + threadIdx.x) >> 5;
    int lane = threadIdx.x & 31;
    if (gw >= 9 * BATCH * NSEQ) return;
    int z = gw / (BATCH * NSEQ);
    const float* hp = &g_h[(size_t)gw * FD];
    const float* a1p = a1 + (size_t)z * FD;
    const float* a2p = a2 + (size_t)z * FD;
    float s1 = 0.0f, s2 = 0.0f;
    #pragma unroll
    for (int i = lane; i < FD; i += 32) {
        float hv = hp[i];
        s1 = fmaf(hv, a1p[i], s1);
        s2 = fmaf(hv, a2p[i], s2);
    }
    #pragma unroll
    for (int off = 16; off > 0; off >>= 1) {
        s1 += __shfl_down_sync(0xffffffffu, s1, off);
        s2 += __shfl_down_sync(0xffffffffu, s2, off);
    }
    if (lane == 0) { g_f1[gw] = s1; g_f2[gw] = s2; }
}

// ---------------- fused sparse softmax + SpMM (layers k=0,1) ----------------
__global__ __launch_bounds__(256) void spmm_kernel(int k, float* __restrict__ Hout) {
    int n = blockIdx.x, b = blockIdx.y;
    int tid = threadIdx.x;

    __shared__ int   list[NSEQ];
    __shared__ float pn[NSEQ];
    __shared__ int   s_cnt;
    __shared__ float red[256];

    float acc = 0.0f;

    for (int t = 0; t < NT; t++) {
        int z = t * 3 + k;
        if (tid == 0) s_cnt = 0;
        __syncthreads();
        if (tid < NWRD) {
            unsigned w = g_mask[k][(((size_t)b * NT + t) * NSEQ + n) * NWRD + tid];
            while (w) {
                int j = (tid << 5) + (__ffs(w) - 1);
                w &= w - 1;
                int p = atomicAdd(&s_cnt, 1);
                list[p] = j;
            }
        }
        __syncthreads();
        int cnt = s_cnt;

        const float* f2p = &g_f2[(size_t)z * BATCH * NSEQ + (size_t)b * NSEQ];
        float f1v = g_f1[(size_t)z * BATCH * NSEQ + (size_t)b * NSEQ + n];
        const float* hp = &g_h[((size_t)z * BATCH + b) * NSEQ * FD];

        if (cnt == 0) {
            float a = 0.0f;
            for (int j = 0; j < NSEQ; j++) a += hp[(size_t)j * FD + tid];
            acc += a * (1.0f / NSEQ);
            __syncthreads();
            continue;
        }

        float lmax = -1e30f;
        for (int i = tid; i < cnt; i += 256) {
            float x = f1v + f2p[list[i]];
            x = (x > 0.0f) ? x : ALPHAV * x;
            pn[i] = x;
            lmax = fmaxf(lmax, x);
        }
        red[tid] = lmax;
        __syncthreads();
        for (int s = 128; s > 0; s >>= 1) {
            if (tid < s) red[tid] = fmaxf(red[tid], red[tid + s]);
            __syncthreads();
        }
        float m = red[0];
        __syncthreads();

        float lsum = 0.0f;
        for (int i = tid; i < cnt; i += 256) {
            float p = __expf(pn[i] - m);
            pn[i] = p;
            lsum += p;
        }
        red[tid] = lsum;
        __syncthreads();
        for (int s = 128; s > 0; s >>= 1) {
            if (tid < s) red[tid] += red[tid + s];
            __syncthreads();
        }
        float inv = 1.0f / red[0];
        __syncthreads();

        int i = 0;
        for (; i + 4 <= cnt; i += 4) {
            int j0 = list[i], j1 = list[i + 1], j2 = list[i + 2], j3 = list[i + 3];
            float p0 = pn[i] * inv, p1 = pn[i + 1] * inv;
            float p2 = pn[i + 2] * inv, p3 = pn[i + 3] * inv;
            float h0 = hp[(size_t)j0 * FD + tid];
            float h1 = hp[(size_t)j1 * FD + tid];
            float h2 = hp[(size_t)j2 * FD + tid];
            float h3 = hp[(size_t)j3 * FD + tid];
            acc = fmaf(p0, h0, acc);
            acc = fmaf(p1, h1, acc);
            acc = fmaf(p2, h2, acc);
            acc = fmaf(p3, h3, acc);
        }
        for (; i < cnt; i++)
            acc = fmaf(pn[i] * inv, hp[(size_t)list[i] * FD + tid], acc);
        __syncthreads();
    }

    Hout[(((size_t)b * NSEQ + n) * NLAY + k) * FD + tid] = acc;
}

// ---------------- dense masked-softmax attention row (k=2) ------------------
__global__ void att_kernel(int t, int k) {
    int i = blockIdx.x, b = blockIdx.y;
    int tid = threadIdx.x;
    int z = t * 3 + k;

    __shared__ float sf2[NSEQ];
    __shared__ unsigned smask[NWRD];
    __shared__ float red[256];

    const float* f2p = &g_f2[(size_t)z * BATCH * NSEQ + (size_t)b * NSEQ];
    for (int j = tid; j < NSEQ; j += 256) sf2[j] = f2p[j];
    if (tid < NWRD)
        smask[tid] = g_mask[k][(((size_t)b * NT + t) * NSEQ + i) * NWRD + tid];
    __syncthreads();

    float f1v = g_f1[(size_t)z * BATCH * NSEQ + (size_t)b * NSEQ + i];

    float e[4];
    bool msk[4];
    float lmax = NEGV;
    #pragma unroll
    for (int q = 0; q < 4; q++) {
        int j = tid + q * 256;
        bool m = (smask[j >> 5] >> (j & 31)) & 1u;
        float x = f1v + sf2[j];
        x = (x > 0.0f) ? x : ALPHAV * x;
        e[q] = m ? x : NEGV;
        msk[q] = m;
        lmax = fmaxf(lmax, e[q]);
    }
    red[tid] = lmax;
    __syncthreads();
    for (int s = 128; s > 0; s >>= 1) {
        if (tid < s) red[tid] = fmaxf(red[tid], red[tid + s]);
        __syncthreads();
    }
    float m = red[0];
    __syncthreads();

    bool empty = (m < -8.9e15f);
    float p[4];
    float lsum = 0.0f;
    #pragma unroll
    for (int q = 0; q < 4; q++) {
        p[q] = empty ? 1.0f : (msk[q] ? __expf(e[q] - m) : 0.0f);
        lsum += p[q];
    }
    red[tid] = lsum;
    __syncthreads();
    for (int s = 128; s > 0; s >>= 1) {
        if (tid < s) red[tid] += red[tid + s];
        __syncthreads();
    }
    float inv = 1.0f / red[0];

    float* arow = &g_att[((size_t)b * NSEQ + i) * NSEQ];
    #pragma unroll
    for (int q = 0; q < 4; q++) arow[tid + q * 256] = p[q] * inv;
}

// ---------------- final combine ---------------------------------------------
__global__ void combine_kernel(const float* __restrict__ Ww, const float* __restrict__ bw,
                               const float* __restrict__ Wc, float* __restrict__ out) {
    int bn = blockIdx.x;
    int tid = threadIdx.x;
    __shared__ float sh[NLAY * FD];
    __shared__ float part[NLAY][128];
    __shared__ float sy[NLAY];

    const float* Hp = &g_H[(size_t)bn * NLAY * FD];
    for (int i = tid; i < NLAY * FD; i += 128) sh[i] = Hp[i];
    __syncthreads();

    float loc[NLAY] = {0.0f, 0.0f, 0.0f};
    if (tid < 100) {
        float wc = Wc[tid];
        float bwv = bw[tid];
        #pragma unroll
        for (int k = 0; k < NLAY; k++) {
            float y = bwv;
            #pragma unroll 8
            for (int i = 0; i < FD; i++)
                y = fmaf(sh[k * FD + i], Ww[i * 100 + tid], y);
            loc[k] = tanhf(y) * wc;
        }
    }
    #pragma unroll
    for (int k = 0; k < NLAY; k++) part[k][tid] = loc[k];
    __syncthreads();
    for (int s = 64; s > 0; s >>= 1) {
        if (tid < s) {
            part[0][tid] += part[0][tid + s];
            part[1][tid] += part[1][tid + s];
            part[2][tid] += part[2][tid + s];
        }
        __syncthreads();
    }
    if (tid == 0) {
        float s0 = part[0][0], s1 = part[1][0], s2 = part[2][0];
        float mx = fmaxf(s0, fmaxf(s1, s2));
        float e0 = __expf(s0 - mx), e1 = __expf(s1 - mx), e2 = __expf(s2 - mx);
        float invs = 1.0f / (e0 + e1 + e2);
        sy[0] = e0 * invs; sy[1] = e1 * invs; sy[2] = e2 * invs;
    }
    __syncthreads();

    float w0 = sy[0], w1 = sy[1], w2 = sy[2];
    for (int f = tid; f < FD; f += 128)
        out[(size_t)bn * FD + f] =
            w0 * sh[f] + w1 * sh[FD + f] + w2 * sh[2 * FD + f];
}

// ---------------- launch ----------------------------------------------------
extern "C" void kernel_launch(void* const* d_in, const int* in_sizes, int n_in,
                              void* d_out, int out_size) {
    const float* adj = (const float*)d_in[0];
    const float* X   = (const float*)d_in[1];
    const float* W   = (const float*)d_in[2];
    const float* a1  = (const float*)d_in[3];
    const float* a2  = (const float*)d_in[4];
    const float* Ww  = (const float*)d_in[5];
    const float* bw  = (const float*)d_in[6];
    const float* Wc  = (const float*)d_in[7];
    float* out = (float*)d_out;

    void *ph, *patt, *pH;
    cudaGetSymbolAddress(&ph, g_h);
    cudaGetSymbolAddress(&patt, g_att);
    cudaGetSymbolAddress(&pH, g_H);
    float* hbuf = (float*)ph;
    float* attbuf = (float*)patt;
    float* Hbuf = (float*)pH;

    // 1. adjacency bitsets + boolean powers
    bits_kernel<<<BATCH * NT * NSEQ, 1024>>>(adj);
    bmm_kernel<<<BATCH * NT * NSEQ, 32>>>(0, 1);
    bmm_kernel<<<BATCH * NT * NSEQ, 32>>>(1, 2);

    // 2. h[t,k] = X @ W[t,k]  (tf32 tensor cores)
    {
        dim3 grid(FD / BN, (BATCH * NSEQ) / BM, 9);
        tgemm<<<grid, 256>>>(X, W, hbuf,
                             IND, IND, FD, FD,
                             0LL, (long long)IND * FD,
                             (long long)BATCH * NSEQ * FD, 0);
    }

    // 3. f1/f2 projections
    f_kernel<<<(9 * BATCH * NSEQ) / 8, 256>>>(a1, a2);

    // 4a. sparse layers k=0,1
    spmm_kernel<<<dim3(NSEQ, BATCH), 256>>>(0, Hbuf);
    spmm_kernel<<<dim3(NSEQ, BATCH), 256>>>(1, Hbuf);

    // 4b. dense layer k=2: masked softmax + tf32 GEMM accumulated over t
    for (int t = 0; t < NT; t++) {
        att_kernel<<<dim3(NSEQ, BATCH), 256>>>(t, 2);
        int z = t * 3 + 2;
        dim3 grid(FD / BN, NSEQ / BM, BATCH);
        tgemm<<<grid, 256>>>(attbuf,
                             hbuf + (size_t)z * BATCH * NSEQ * FD,
                             Hbuf + 2 * FD,
                             NSEQ, NSEQ, FD, NLAY * FD,
                             (long long)NSEQ * NSEQ,
                             (long long)NSEQ * FD,
                             (long long)NSEQ * NLAY * FD,
                             t > 0 ? 1 : 0);
    }

    // 5. combine
    combine_kernel<<<BATCH * NSEQ, 128>>>(Ww, bw, Wc, out);
}